// round 3
// baseline (speedup 1.0000x reference)
#include <cuda_runtime.h>
#include <math.h>

// Problem constants
#define BATCH 512
#define SEQ   80
#define NV    36
#define NC    16
#define ANGLE 128
#define EMB   64
#define HID   512
#define FEAT  2176
#define INDIM 2240   // EMB + FEAT
#define GATES 2048   // 4*HID

// ---------------- scratch (single __device__ buffer, offsets in floats) ----
#define O_TDENSE 0u
#define O_TFEAT  1114112u            // 512*2176
#define O_XV     2228224u
#define O_XO     3375104u            // + 512*2240
#define O_GV     4521984u
#define O_GO     5570560u            // + 512*2048
#define O_HCV    6619136u
#define O_HCO    7143424u            // + 512*1024
#define O_TAVV   7667712u
#define O_TAVO   7929856u            // + 512*512
#define O_HC2    8192000u
#define O_TCAND  8716288u
#define SCRATCH_FLOATS 9830400u

__device__ float g_scratch[SCRATCH_FLOATS];

// output offsets (floats) in d_out
#define OFF_H1V   0u
#define OFF_H1O   262144u
#define OFF_C1V   524288u
#define OFF_C1O   786432u
#define OFF_LOGIT 1048576u
#define OFF_HTV   1056768u
#define OFF_HTO   1318912u

// ---------------- generic NT SGEMM: C = A[M,K] * B[N,K]^T ------------------
// 64x64 tile, BK=16, 256 threads, 4x4 per-thread microtile, float4 paths.
// Optional: accumulate into C, add bias[n], tanh epilogue, dual write C2.
#define BM 64
#define BN 64
#define BK 16

__global__ __launch_bounds__(256) void gemm_nt_kernel(
    const float* __restrict__ A, const float* __restrict__ Bw,
    float* __restrict__ C, float* __restrict__ C2,
    const float* __restrict__ bias,
    int M, int N, int K, int lda, int ldb, int ldc, int ldc2,
    int accumulate, int do_tanh)
{
    __shared__ float As[BK][BM];
    __shared__ float Bs[BK][BN];
    const int tid = threadIdx.x;
    const int m0 = blockIdx.y * BM;
    const int n0 = blockIdx.x * BN;
    const int lr = tid >> 2;          // 0..63 (row within tile)
    const int lc = (tid & 3) * 4;     // 0,4,8,12 (col within BK)
    const int ty = tid >> 4;          // 0..15
    const int tx = tid & 15;          // 0..15

    float acc[4][4];
#pragma unroll
    for (int i = 0; i < 4; i++)
#pragma unroll
        for (int j = 0; j < 4; j++) acc[i][j] = 0.f;

    const float* Aptr = A + (size_t)(m0 + lr) * lda + lc;
    const float* Bptr = Bw + (size_t)(n0 + lr) * ldb + lc;

    for (int k0 = 0; k0 < K; k0 += BK) {
        float4 av = *reinterpret_cast<const float4*>(Aptr + k0);
        float4 bv = *reinterpret_cast<const float4*>(Bptr + k0);
        __syncthreads();
        As[lc + 0][lr] = av.x; As[lc + 1][lr] = av.y;
        As[lc + 2][lr] = av.z; As[lc + 3][lr] = av.w;
        Bs[lc + 0][lr] = bv.x; Bs[lc + 1][lr] = bv.y;
        Bs[lc + 2][lr] = bv.z; Bs[lc + 3][lr] = bv.w;
        __syncthreads();
#pragma unroll
        for (int kk = 0; kk < BK; kk++) {
            float4 a4 = *reinterpret_cast<const float4*>(&As[kk][ty * 4]);
            float4 b4 = *reinterpret_cast<const float4*>(&Bs[kk][tx * 4]);
            float a[4] = {a4.x, a4.y, a4.z, a4.w};
            float b[4] = {b4.x, b4.y, b4.z, b4.w};
#pragma unroll
            for (int i = 0; i < 4; i++)
#pragma unroll
                for (int j = 0; j < 4; j++) acc[i][j] = fmaf(a[i], b[j], acc[i][j]);
        }
    }

#pragma unroll
    for (int i = 0; i < 4; i++) {
        const int m = m0 + ty * 4 + i;
#pragma unroll
        for (int j = 0; j < 4; j++) {
            const int n = n0 + tx * 4 + j;
            float v = acc[i][j];
            if (accumulate) v += C[(size_t)m * ldc + n];
            if (bias) v += bias[n];
            if (do_tanh) v = tanhf(v);
            C[(size_t)m * ldc + n] = v;
            if (C2) C2[(size_t)m * ldc2 + n] = v;
        }
    }
}

// ---------------- fused object/feature attention (online softmax) ----------
// One block per batch row b. out[b, :] = softmax(feat[b] @ target[b]) @ feat[b]
__global__ __launch_bounds__(256) void attn_obj_kernel(
    const float* __restrict__ feat, const float* __restrict__ target,
    const int* __restrict__ mask, float* __restrict__ outp, int out_ld)
{
    __shared__ float tgt[FEAT];
    __shared__ float acc[FEAT];
    __shared__ float row[FEAT];
    __shared__ float red[8];
    __shared__ float s_w, s_sc, s_d;
    const int b = blockIdx.x, tid = threadIdx.x;

    for (int j = tid; j < FEAT; j += 256) {
        tgt[j] = target[(size_t)b * FEAT + j];
        acc[j] = 0.f;
    }
    float m_run = -3.0e38f, d_run = 0.f;
    __syncthreads();

    for (int s = 0; s < NV; s++) {
        const float* fr = feat + ((size_t)b * NV + s) * FEAT;
        float p = 0.f;
        for (int j = tid; j < FEAT; j += 256) {
            float x = fr[j];
            row[j] = x;
            p = fmaf(x, tgt[j], p);
        }
#pragma unroll
        for (int o = 16; o > 0; o >>= 1) p += __shfl_xor_sync(~0u, p, o);
        if ((tid & 31) == 0) red[tid >> 5] = p;
        __syncthreads();
        if (tid == 0) {
            float l = red[0] + red[1] + red[2] + red[3] + red[4] + red[5] + red[6] + red[7];
            if (mask && mask[b * NV + s]) l = -1e30f;
            float nm = fmaxf(m_run, l);
            float sc = expf(m_run - nm);
            float w  = expf(l - nm);
            m_run = nm;
            d_run = d_run * sc + w;
            s_w = w; s_sc = sc; s_d = d_run;
        }
        __syncthreads();
        const float w = s_w, sc = s_sc;
        for (int j = tid; j < FEAT; j += 256) acc[j] = fmaf(w, row[j], acc[j] * sc);
        __syncthreads();
    }
    const float dinv = 1.f / s_d;
    for (int j = tid; j < FEAT; j += 256)
        outp[(size_t)b * out_ld + j] = acc[j] * dinv;
}

// ---------------- fused masked context attention (two-pass, 80 logits) -----
__global__ __launch_bounds__(256) void attn_ctx_kernel(
    const float* __restrict__ ctx, const float* __restrict__ target,
    const int* __restrict__ mask, float* __restrict__ outp, int out_ld)
{
    __shared__ float tgt[HID];
    __shared__ float lg[SEQ];
    __shared__ float p[SEQ];
    __shared__ float s_d;
    const int b = blockIdx.x, tid = threadIdx.x;
    const int lane = tid & 31, w = tid >> 5;

    for (int j = tid; j < HID; j += 256) tgt[j] = target[(size_t)b * HID + j];
    __syncthreads();

    for (int s = w; s < SEQ; s += 8) {
        const float* cr = ctx + ((size_t)b * SEQ + s) * HID;
        float acc = 0.f;
        for (int j = lane; j < HID; j += 32) acc = fmaf(cr[j], tgt[j], acc);
#pragma unroll
        for (int o = 16; o > 0; o >>= 1) acc += __shfl_xor_sync(~0u, acc, o);
        if (lane == 0) lg[s] = mask[b * SEQ + s] ? -1e30f : acc;
    }
    __syncthreads();
    if (tid == 0) {
        float m = -3.0e38f;
        for (int s = 0; s < SEQ; s++) m = fmaxf(m, lg[s]);
        float d = 0.f;
        for (int s = 0; s < SEQ; s++) { float e = expf(lg[s] - m); p[s] = e; d += e; }
        s_d = d;
    }
    __syncthreads();
    const float dinv = 1.f / s_d;
    for (int j = tid; j < HID; j += 256) {
        float sum = 0.f;
        for (int s = 0; s < SEQ; s++)
            sum = fmaf(p[s], ctx[((size_t)b * SEQ + s) * HID + j], sum);
        outp[(size_t)b * out_ld + j] = sum * dinv;
    }
}

// ---------------- LSTM cell elementwise --------------------------------
__global__ __launch_bounds__(256) void lstm_cell_kernel(
    const float* __restrict__ gates, const float* __restrict__ bih,
    const float* __restrict__ bhh, const float* __restrict__ c0,
    float* __restrict__ h_out, float* __restrict__ c_out,
    float* __restrict__ h_out2, int ld2)
{
    const int idx = blockIdx.x * 256 + threadIdx.x;   // < 512*512
    const int b = idx >> 9, j = idx & 511;
    const float* gr = gates + (size_t)b * GATES;
    float gi = gr[j]        + bih[j]        + bhh[j];
    float gf = gr[512 + j]  + bih[512 + j]  + bhh[512 + j];
    float gg = gr[1024 + j] + bih[1024 + j] + bhh[1024 + j];
    float go = gr[1536 + j] + bih[1536 + j] + bhh[1536 + j];
    float si = 1.f / (1.f + expf(-gi));
    float sf = 1.f / (1.f + expf(-gf));
    float so = 1.f / (1.f + expf(-go));
    float c1 = sf * c0[idx] + si * tanhf(gg);
    float h1 = so * tanhf(c1);
    h_out[idx] = h1;
    c_out[idx] = c1;
    h_out2[(size_t)b * ld2 + j] = h1;
}

// ---------------- candidate logits: warp per (b,c) dot over FEAT -----------
__global__ __launch_bounds__(256) void cand_logits_kernel(
    const float* __restrict__ cand, const float* __restrict__ T,
    float* __restrict__ out)
{
    const int wid = (blockIdx.x * 256 + threadIdx.x) >> 5;   // 0..8191
    const int lane = threadIdx.x & 31;
    const int b = wid >> 4, c = wid & 15;
    const float* cr = cand + ((size_t)b * NC + c) * FEAT;
    const float* tr = T + (size_t)b * FEAT;
    float acc = 0.f;
    for (int j = lane; j < FEAT; j += 32) acc = fmaf(cr[j], tr[j], acc);
#pragma unroll
    for (int o = 16; o > 0; o >>= 1) acc += __shfl_xor_sync(~0u, acc, o);
    if (lane == 0) out[wid] = acc;
}

// ---------------- launch ---------------------------------------------------
static inline void gemm(const float* A, const float* B, float* C, int M, int N,
                        int K, int lda, int ldb, int ldc,
                        float* C2 = nullptr, int ldc2 = 0,
                        const float* bias = nullptr, int accumulate = 0,
                        int do_tanh = 0)
{
    dim3 grid(N / BN, M / BM);
    gemm_nt_kernel<<<grid, 256>>>(A, B, C, C2, bias, M, N, K, lda, ldb, ldc,
                                  ldc2, accumulate, do_tanh);
}

extern "C" void kernel_launch(void* const* d_in, const int* in_sizes, int n_in,
                              void* d_out, int out_size)
{
    const float* action    = (const float*)d_in[0];
    const float* cand_feat = (const float*)d_in[1];
    const float* prev_h1_v = (const float*)d_in[2];
    const float* prev_h1_o = (const float*)d_in[3];
    // d_in[4] = c_0_v (unused by reference)
    const float* c_0_o     = (const float*)d_in[5];
    const float* ctx       = (const float*)d_in[6];
    const int*   ctx_mask  = (const int*)d_in[7];
    const float* feature   = (const float*)d_in[8];
    const float* denseObj  = (const float*)d_in[9];
    const int*   obj_mask  = (const int*)d_in[10];
    const float* W_emb     = (const float*)d_in[11];
    const float* b_emb     = (const float*)d_in[12];
    const float* Wih_v     = (const float*)d_in[13];
    const float* Whh_v     = (const float*)d_in[14];
    const float* bih_v     = (const float*)d_in[15];
    const float* bhh_v     = (const float*)d_in[16];
    const float* Wih_o     = (const float*)d_in[17];
    const float* Whh_o     = (const float*)d_in[18];
    const float* bih_o     = (const float*)d_in[19];
    const float* bhh_o     = (const float*)d_in[20];
    const float* Wq_feat   = (const float*)d_in[21];
    const float* Wq_dense  = (const float*)d_in[22];
    const float* Wq_av     = (const float*)d_in[23];
    const float* Wo_av     = (const float*)d_in[24];
    const float* Wq_ao     = (const float*)d_in[25];
    const float* Wo_ao     = (const float*)d_in[26];
    const float* Wq_cand   = (const float*)d_in[27];
    float* out = (float*)d_out;

    float* scr = nullptr;
    cudaGetSymbolAddress((void**)&scr, g_scratch);

    // 1) action embeds -> tanh(action @ W_emb^T + b) into Xv[:, :64] and Xo[:, :64]
    gemm(action, W_emb, scr + O_XV, BATCH, EMB, ANGLE, ANGLE, ANGLE, INDIM,
         scr + O_XO, INDIM, b_emb, 0, 1);

    // 2) attention targets
    gemm(prev_h1_o, Wq_dense, scr + O_TDENSE, BATCH, FEAT, HID, HID, HID, FEAT);
    gemm(prev_h1_v, Wq_feat,  scr + O_TFEAT,  BATCH, FEAT, HID, HID, HID, FEAT);

    // 3) fused object/feature attention -> Xo[:,64:], Xv[:,64:]
    attn_obj_kernel<<<BATCH, 256>>>(denseObj, scr + O_TDENSE, obj_mask,
                                    scr + O_XO + EMB, INDIM);
    attn_obj_kernel<<<BATCH, 256>>>(feature, scr + O_TFEAT, nullptr,
                                    scr + O_XV + EMB, INDIM);

    // 4) LSTM gate GEMMs (input + recurrent, accumulated)
    gemm(scr + O_XV, Wih_v, scr + O_GV, BATCH, GATES, INDIM, INDIM, INDIM, GATES);
    gemm(prev_h1_v,  Whh_v, scr + O_GV, BATCH, GATES, HID, HID, HID, GATES,
         nullptr, 0, nullptr, 1, 0);
    gemm(scr + O_XO, Wih_o, scr + O_GO, BATCH, GATES, INDIM, INDIM, INDIM, GATES);
    gemm(prev_h1_o,  Whh_o, scr + O_GO, BATCH, GATES, HID, HID, HID, GATES,
         nullptr, 0, nullptr, 1, 0);

    // 5) LSTM cells (both use c_0_o, per reference)
    lstm_cell_kernel<<<(BATCH * HID) / 256, 256>>>(
        scr + O_GV, bih_v, bhh_v, c_0_o, out + OFF_H1V, out + OFF_C1V,
        scr + O_HCV + HID, 2 * HID);
    lstm_cell_kernel<<<(BATCH * HID) / 256, 256>>>(
        scr + O_GO, bih_o, bhh_o, c_0_o, out + OFF_H1O, out + OFF_C1O,
        scr + O_HCO + HID, 2 * HID);

    // 6) context attention targets
    gemm(out + OFF_H1V, Wq_av, scr + O_TAVV, BATCH, HID, HID, HID, HID, HID);
    gemm(out + OFF_H1O, Wq_ao, scr + O_TAVO, BATCH, HID, HID, HID, HID, HID);

    // 7) masked context attention -> wctx into htcat[:, :512]
    attn_ctx_kernel<<<BATCH, 256>>>(ctx, scr + O_TAVV, ctx_mask,
                                    scr + O_HCV, 2 * HID);
    attn_ctx_kernel<<<BATCH, 256>>>(ctx, scr + O_TAVO, ctx_mask,
                                    scr + O_HCO, 2 * HID);

    // 8) h_tilde = tanh([wctx, h1] @ Wo^T) -> d_out and cand-concat buffer
    gemm(scr + O_HCV, Wo_av, out + OFF_HTV, BATCH, HID, 2 * HID, 2 * HID,
         2 * HID, HID, scr + O_HC2, 2 * HID, nullptr, 0, 1);
    gemm(scr + O_HCO, Wo_ao, out + OFF_HTO, BATCH, HID, 2 * HID, 2 * HID,
         2 * HID, HID, scr + O_HC2 + HID, 2 * HID, nullptr, 0, 1);

    // 9) candidate target + logits
    gemm(scr + O_HC2, Wq_cand, scr + O_TCAND, BATCH, FEAT, 2 * HID, 2 * HID,
         2 * HID, FEAT);
    cand_logits_kernel<<<(BATCH * NC * 32) / 256, 256>>>(
        cand_feat, scr + O_TCAND, out + OFF_LOGIT);
}

// round 6
// speedup vs baseline: 1.5936x; 1.5936x over previous
#include <cuda_runtime.h>
#include <math.h>
#include <stdint.h>

#define BATCH 512
#define SEQ   80
#define NV    36
#define NC    16
#define ANGLE 128
#define EMB   64
#define HID   512
#define FEAT  2176
#define INDIM 2240
#define GATES 2048
#define FEAT4 544

// ---------------- scratch ----------------
#define O_TDENSE 0u
#define O_TFEAT  1114112u
#define O_XV     2228224u
#define O_XO     3375104u
#define O_GV     4521984u
#define O_GO     5570560u
#define O_HCV    6619136u
#define O_HCO    7143424u
#define O_TAVV   7667712u
#define O_TAVO   7929856u
#define O_HC2    8192000u
#define O_TCAND  8716288u
#define SCRATCH_FLOATS 9830400u
__device__ float g_scratch[SCRATCH_FLOATS];

#define OFF_H1V   0u
#define OFF_H1O   262144u
#define OFF_C1V   524288u
#define OFF_C1O   786432u
#define OFF_LOGIT 1048576u
#define OFF_HTV   1056768u
#define OFF_HTO   1318912u

// ==================== low-level helpers (sm_80-era, valid on sm_103) =======
__device__ __forceinline__ uint32_t smem_u32(const void* p) {
    uint32_t a;
    asm("{ .reg .u64 t; cvta.to.shared.u64 t, %1; cvt.u32.u64 %0, t; }"
        : "=r"(a) : "l"(p));
    return a;
}
__device__ __forceinline__ void cp16(uint32_t dst, const void* src) {
    asm volatile("cp.async.cg.shared.global [%0], [%1], 16;"
                 :: "r"(dst), "l"(src));
}
#define CP_COMMIT() asm volatile("cp.async.commit_group;" ::: "memory")
#define CP_WAIT1()  asm volatile("cp.async.wait_group 1;" ::: "memory")
#define CP_WAIT0()  asm volatile("cp.async.wait_group 0;" ::: "memory")

__device__ __forceinline__ uint32_t tf32_of(float x) {
    uint32_t r;
    asm("cvt.rna.tf32.f32 %0, %1;" : "=r"(r) : "f"(x));
    return r;
}
__device__ __forceinline__ void split_tf32(float x, uint32_t& hi, uint32_t& lo) {
    hi = tf32_of(x);
    lo = tf32_of(x - __uint_as_float(hi));
}
__device__ __forceinline__ void mma_tf32(float* d, const uint32_t* a, const uint32_t* b) {
    asm volatile(
        "mma.sync.aligned.m16n8k8.row.col.f32.tf32.tf32.f32 "
        "{%0,%1,%2,%3}, {%4,%5,%6,%7}, {%8,%9}, {%0,%1,%2,%3};"
        : "+f"(d[0]), "+f"(d[1]), "+f"(d[2]), "+f"(d[3])
        : "r"(a[0]), "r"(a[1]), "r"(a[2]), "r"(a[3]), "r"(b[0]), "r"(b[1]));
}

// ==================== 3xTF32 mma.sync GEMM ====================
// C[M,N] = A1[M,K1]*B1[N,K1]^T (+ A2[M,K2]*B2[N,K2]^T).
// Tile 128x64, BK=32, cp.async double buffer, padded smem rows (stride 36).
// 8 warps in 4x2 grid; warp tile 32x32 = 2(m) x 4(n) m16n8 fragments.
#define AS_FLOATS 4608     // 128*36
#define BS_FLOATS 2304     // 64*36
#define BUF_FLOATS (AS_FLOATS + BS_FLOATS)   // 6912
#define GEMM_SMEM (2 * BUF_FLOATS * 4)       // 55296 bytes

__global__ __launch_bounds__(256) void gemm_tc_kernel(
    const float* __restrict__ A1, const float* __restrict__ B1, int K1, int lda1, int ldb1,
    const float* __restrict__ A2, const float* __restrict__ B2, int K2, int lda2, int ldb2,
    float* __restrict__ C, int ldc, float* __restrict__ C2, int ldc2,
    const float* __restrict__ bias, int do_tanh)
{
    extern __shared__ float sm[];
    const int tid = threadIdx.x;
    const int wid = tid >> 5, lane = tid & 31;
    const int wm = wid >> 1, wn = wid & 1;           // warp grid 4x2
    const int m0 = blockIdx.y * 128, n0 = blockIdx.x * 64;
    const uint32_t sm_u = smem_u32(sm);

    const int nc1 = K1 >> 5;
    const int nc  = nc1 + (K2 >> 5);

    float acc[2][4][4];
#pragma unroll
    for (int i = 0; i < 2; i++)
#pragma unroll
        for (int j = 0; j < 4; j++)
#pragma unroll
            for (int c = 0; c < 4; c++) acc[i][j][c] = 0.f;

    // async-stage one K-chunk (32 floats wide) into buffer `buf`
    auto stage = [&](int kc, int buf) {
        const float *A, *B;
        int lda, ldb, k0;
        if (kc < nc1) { A = A1; B = B1; lda = lda1; ldb = ldb1; k0 = kc << 5; }
        else          { A = A2; B = B2; lda = lda2; ldb = ldb2; k0 = (kc - nc1) << 5; }
        const uint32_t abase = sm_u + (uint32_t)buf * BUF_FLOATS * 4u;
        const uint32_t bbase = abase + AS_FLOATS * 4u;
#pragma unroll
        for (int i = 0; i < 4; i++) {                 // A: 1024 float4
            const int idx = tid + 256 * i;
            const int row = idx >> 3, q = idx & 7;
            cp16(abase + (uint32_t)(row * 36 + q * 4) * 4u,
                 A + (size_t)(m0 + row) * lda + k0 + q * 4);
        }
#pragma unroll
        for (int i = 0; i < 2; i++) {                 // B: 512 float4
            const int idx = tid + 256 * i;
            const int row = idx >> 3, q = idx & 7;
            cp16(bbase + (uint32_t)(row * 36 + q * 4) * 4u,
                 B + (size_t)(n0 + row) * ldb + k0 + q * 4);
        }
    };

    stage(0, 0);
    CP_COMMIT();

    for (int kc = 0; kc < nc; kc++) {
        const int buf = kc & 1;
        if (kc + 1 < nc) { stage(kc + 1, buf ^ 1); CP_COMMIT(); CP_WAIT1(); }
        else             { CP_WAIT0(); }
        __syncthreads();

        const float* As = sm + buf * BUF_FLOATS;
        const float* Bs = As + AS_FLOATS;
        const int ar = (lane >> 2), ac = (lane & 3);

#pragma unroll
        for (int ks = 0; ks < 4; ks++) {
            uint32_t ah[2][4], al[2][4], bh[4][2], bl[4][2];
#pragma unroll
            for (int mt = 0; mt < 2; mt++) {
                const float* p = As + (wm * 32 + mt * 16 + ar) * 36 + ks * 8 + ac;
                split_tf32(p[0],       ah[mt][0], al[mt][0]);
                split_tf32(p[8 * 36],  ah[mt][1], al[mt][1]);
                split_tf32(p[4],       ah[mt][2], al[mt][2]);
                split_tf32(p[8 * 36 + 4], ah[mt][3], al[mt][3]);
            }
#pragma unroll
            for (int nt = 0; nt < 4; nt++) {
                const float* p = Bs + (wn * 32 + nt * 8 + ar) * 36 + ks * 8 + ac;
                split_tf32(p[0], bh[nt][0], bl[nt][0]);
                split_tf32(p[4], bh[nt][1], bl[nt][1]);
            }
#pragma unroll
            for (int mt = 0; mt < 2; mt++)
#pragma unroll
                for (int nt = 0; nt < 4; nt++) {
                    mma_tf32(acc[mt][nt], ah[mt], bh[nt]);
                    mma_tf32(acc[mt][nt], ah[mt], bl[nt]);
                    mma_tf32(acc[mt][nt], al[mt], bh[nt]);
                }
        }
        __syncthreads();
    }

    // epilogue
    const int r_in = lane >> 2, c_in = 2 * (lane & 3);
#pragma unroll
    for (int mt = 0; mt < 2; mt++) {
#pragma unroll
        for (int nt = 0; nt < 4; nt++) {
            const int r0 = m0 + wm * 32 + mt * 16 + r_in;
            const int cc = n0 + wn * 32 + nt * 8 + c_in;
            float v0 = acc[mt][nt][0], v1 = acc[mt][nt][1];
            float v2 = acc[mt][nt][2], v3 = acc[mt][nt][3];
            if (bias) {
                const float b0 = bias[cc], b1 = bias[cc + 1];
                v0 += b0; v1 += b1; v2 += b0; v3 += b1;
            }
            if (do_tanh) {
                v0 = tanhf(v0); v1 = tanhf(v1); v2 = tanhf(v2); v3 = tanhf(v3);
            }
            *(float2*)(C + (size_t)r0 * ldc + cc)       = make_float2(v0, v1);
            *(float2*)(C + (size_t)(r0 + 8) * ldc + cc) = make_float2(v2, v3);
            if (C2) {
                *(float2*)(C2 + (size_t)r0 * ldc2 + cc)       = make_float2(v0, v1);
                *(float2*)(C2 + (size_t)(r0 + 8) * ldc2 + cc) = make_float2(v2, v3);
            }
        }
    }
}

// ==================== object attention: registers + prefetch ===============
__global__ __launch_bounds__(256) void attn_obj_kernel(
    const float* __restrict__ feat, const float* __restrict__ target,
    const int* __restrict__ mask, float* __restrict__ outp, int out_ld)
{
    __shared__ float red[2][8];
    __shared__ int msk[NV];
    const int b = blockIdx.x, tid = threadIdx.x;
    const int wid = tid >> 5, lane = tid & 31;
    if (tid < NV) msk[tid] = mask ? mask[b * NV + tid] : 0;

    const bool v2 = tid < (FEAT4 - 512);   // tid < 32
    const float4* tg4 = (const float4*)(target + (size_t)b * FEAT);
    float4 tg0 = tg4[tid], tg1 = tg4[tid + 256];
    float4 tg2 = v2 ? tg4[tid + 512] : make_float4(0.f, 0.f, 0.f, 0.f);
    float4 ac0 = make_float4(0.f, 0.f, 0.f, 0.f), ac1 = ac0, ac2 = ac0;

    const float4* f4 = (const float4*)(feat + (size_t)b * NV * FEAT);
    float4 cu0 = f4[tid], cu1 = f4[tid + 256];
    float4 cu2 = v2 ? f4[tid + 512] : make_float4(0.f, 0.f, 0.f, 0.f);

    float m_run = -3.0e38f, d_run = 0.f;
    __syncthreads();

    for (int s = 0; s < NV; s++) {
        float4 nx0 = cu0, nx1 = cu1, nx2 = cu2;
        if (s + 1 < NV) {
            const float4* fn = f4 + (size_t)(s + 1) * FEAT4;
            nx0 = fn[tid]; nx1 = fn[tid + 256];
            if (v2) nx2 = fn[tid + 512];
        }
        float p = cu0.x*tg0.x + cu0.y*tg0.y + cu0.z*tg0.z + cu0.w*tg0.w
                + cu1.x*tg1.x + cu1.y*tg1.y + cu1.z*tg1.z + cu1.w*tg1.w
                + cu2.x*tg2.x + cu2.y*tg2.y + cu2.z*tg2.z + cu2.w*tg2.w;
#pragma unroll
        for (int o = 16; o > 0; o >>= 1) p += __shfl_xor_sync(~0u, p, o);
        if (lane == 0) red[s & 1][wid] = p;
        __syncthreads();
        float l = ((red[s&1][0] + red[s&1][1]) + (red[s&1][2] + red[s&1][3]))
                + ((red[s&1][4] + red[s&1][5]) + (red[s&1][6] + red[s&1][7]));
        if (msk[s]) l = -1e30f;
        const float nm = fmaxf(m_run, l);
        const float sc = __expf(m_run - nm);
        const float w  = __expf(l - nm);
        m_run = nm;
        d_run = d_run * sc + w;
        ac0.x = ac0.x*sc + w*cu0.x; ac0.y = ac0.y*sc + w*cu0.y;
        ac0.z = ac0.z*sc + w*cu0.z; ac0.w = ac0.w*sc + w*cu0.w;
        ac1.x = ac1.x*sc + w*cu1.x; ac1.y = ac1.y*sc + w*cu1.y;
        ac1.z = ac1.z*sc + w*cu1.z; ac1.w = ac1.w*sc + w*cu1.w;
        ac2.x = ac2.x*sc + w*cu2.x; ac2.y = ac2.y*sc + w*cu2.y;
        ac2.z = ac2.z*sc + w*cu2.z; ac2.w = ac2.w*sc + w*cu2.w;
        cu0 = nx0; cu1 = nx1; cu2 = nx2;
    }
    const float di = 1.f / d_run;
    float4* op = (float4*)(outp + (size_t)b * out_ld);
    op[tid]       = make_float4(ac0.x*di, ac0.y*di, ac0.z*di, ac0.w*di);
    op[tid + 256] = make_float4(ac1.x*di, ac1.y*di, ac1.z*di, ac1.w*di);
    if (v2)
        op[tid + 512] = make_float4(ac2.x*di, ac2.y*di, ac2.z*di, ac2.w*di);
}

// ==================== fused ctx attention (v + o) ====================
#define CTX_SMEM (SEQ * HID * 4)
__global__ __launch_bounds__(256) void attn_ctx_kernel(
    const float* __restrict__ ctx, const float* __restrict__ tgtV,
    const float* __restrict__ tgtO, const int* __restrict__ mask,
    float* __restrict__ outV, float* __restrict__ outO, int out_ld)
{
    extern __shared__ float cs[];   // [SEQ][HID]
    __shared__ float tv[HID], tw[HID];
    __shared__ float lgv[SEQ], lgo[SEQ], pv[SEQ], po[SEQ];
    __shared__ float sdv, sdo;
    const int b = blockIdx.x, tid = threadIdx.x;
    const int wid = tid >> 5, lane = tid & 31;

    const float4* src = (const float4*)(ctx + (size_t)b * SEQ * HID);
    float4* cs4 = (float4*)cs;
    for (int i = tid; i < SEQ * HID / 4; i += 256) cs4[i] = src[i];
    for (int j = tid; j < HID; j += 256) {
        tv[j] = tgtV[(size_t)b * HID + j];
        tw[j] = tgtO[(size_t)b * HID + j];
    }
    __syncthreads();

    for (int s = wid; s < SEQ; s += 8) {
        const float* r = cs + s * HID;
        float av = 0.f, ao = 0.f;
#pragma unroll 4
        for (int j = lane; j < HID; j += 32) {
            const float x = r[j];
            av = fmaf(x, tv[j], av);
            ao = fmaf(x, tw[j], ao);
        }
#pragma unroll
        for (int o = 16; o > 0; o >>= 1) {
            av += __shfl_xor_sync(~0u, av, o);
            ao += __shfl_xor_sync(~0u, ao, o);
        }
        if (lane == 0) {
            const int mk = mask[b * SEQ + s];
            lgv[s] = mk ? -1e30f : av;
            lgo[s] = mk ? -1e30f : ao;
        }
    }
    __syncthreads();
    if (tid == 0) {
        float m = -3.0e38f;
        for (int s = 0; s < SEQ; s++) m = fmaxf(m, lgv[s]);
        float d = 0.f;
        for (int s = 0; s < SEQ; s++) { const float e = __expf(lgv[s] - m); pv[s] = e; d += e; }
        sdv = d;
    }
    if (tid == 32) {
        float m = -3.0e38f;
        for (int s = 0; s < SEQ; s++) m = fmaxf(m, lgo[s]);
        float d = 0.f;
        for (int s = 0; s < SEQ; s++) { const float e = __expf(lgo[s] - m); po[s] = e; d += e; }
        sdo = d;
    }
    __syncthreads();
    const float dv = 1.f / sdv, dw = 1.f / sdo;
    for (int j = tid; j < HID; j += 256) {
        float sv = 0.f, so = 0.f;
#pragma unroll 4
        for (int s = 0; s < SEQ; s++) {
            const float x = cs[s * HID + j];
            sv = fmaf(pv[s], x, sv);
            so = fmaf(po[s], x, so);
        }
        outV[(size_t)b * out_ld + j] = sv * dv;
        outO[(size_t)b * out_ld + j] = so * dw;
    }
}

// ==================== LSTM cell ====================
__global__ __launch_bounds__(256) void lstm_cell_kernel(
    const float* __restrict__ gates, const float* __restrict__ bih,
    const float* __restrict__ bhh, const float* __restrict__ c0,
    float* __restrict__ h_out, float* __restrict__ c_out,
    float* __restrict__ h_out2, int ld2)
{
    const int idx = blockIdx.x * 256 + threadIdx.x;
    const int b = idx >> 9, j = idx & 511;
    const float* gr = gates + (size_t)b * GATES;
    const float gi = gr[j]        + bih[j]        + bhh[j];
    const float gf = gr[512 + j]  + bih[512 + j]  + bhh[512 + j];
    const float gg = gr[1024 + j] + bih[1024 + j] + bhh[1024 + j];
    const float go = gr[1536 + j] + bih[1536 + j] + bhh[1536 + j];
    const float si = 1.f / (1.f + expf(-gi));
    const float sf = 1.f / (1.f + expf(-gf));
    const float so = 1.f / (1.f + expf(-go));
    const float c1 = sf * c0[idx] + si * tanhf(gg);
    const float h1 = so * tanhf(c1);
    h_out[idx] = h1;
    c_out[idx] = c1;
    h_out2[(size_t)b * ld2 + j] = h1;
}

// ==================== candidate logits ====================
__global__ __launch_bounds__(256) void cand_logits_kernel(
    const float* __restrict__ cand, const float* __restrict__ T,
    float* __restrict__ out)
{
    const int w = (blockIdx.x * 256 + threadIdx.x) >> 5;
    const int lane = threadIdx.x & 31;
    const int b = w >> 4, c = w & 15;
    const float4* cr = (const float4*)(cand + ((size_t)b * NC + c) * FEAT);
    const float4* tr = (const float4*)(T + (size_t)b * FEAT);
    float acc = 0.f;
    for (int j = lane; j < FEAT4; j += 32) {
        const float4 a = cr[j], t = tr[j];
        acc += a.x*t.x + a.y*t.y + a.z*t.z + a.w*t.w;
    }
#pragma unroll
    for (int o = 16; o > 0; o >>= 1) acc += __shfl_xor_sync(~0u, acc, o);
    if (lane == 0) out[w] = acc;
}

// ==================== launch ====================
static void gemm_tc(const float* A1, const float* B1, int K1, int lda1, int ldb1,
                    const float* A2, const float* B2, int K2, int lda2, int ldb2,
                    float* C, int ldc, int M, int N,
                    float* C2 = nullptr, int ldc2 = 0,
                    const float* bias = nullptr, int do_tanh = 0)
{
    dim3 grid(N / 64, M / 128);
    gemm_tc_kernel<<<grid, 256, GEMM_SMEM>>>(A1, B1, K1, lda1, ldb1,
                                             A2, B2, K2, lda2, ldb2,
                                             C, ldc, C2, ldc2, bias, do_tanh);
}

extern "C" void kernel_launch(void* const* d_in, const int* in_sizes, int n_in,
                              void* d_out, int out_size)
{
    const float* action    = (const float*)d_in[0];
    const float* cand_feat = (const float*)d_in[1];
    const float* prev_h1_v = (const float*)d_in[2];
    const float* prev_h1_o = (const float*)d_in[3];
    const float* c_0_o     = (const float*)d_in[5];
    const float* ctx       = (const float*)d_in[6];
    const int*   ctx_mask  = (const int*)d_in[7];
    const float* feature   = (const float*)d_in[8];
    const float* denseObj  = (const float*)d_in[9];
    const int*   obj_mask  = (const int*)d_in[10];
    const float* W_emb     = (const float*)d_in[11];
    const float* b_emb     = (const float*)d_in[12];
    const float* Wih_v     = (const float*)d_in[13];
    const float* Whh_v     = (const float*)d_in[14];
    const float* bih_v     = (const float*)d_in[15];
    const float* bhh_v     = (const float*)d_in[16];
    const float* Wih_o     = (const float*)d_in[17];
    const float* Whh_o     = (const float*)d_in[18];
    const float* bih_o     = (const float*)d_in[19];
    const float* bhh_o     = (const float*)d_in[20];
    const float* Wq_feat   = (const float*)d_in[21];
    const float* Wq_dense  = (const float*)d_in[22];
    const float* Wq_av     = (const float*)d_in[23];
    const float* Wo_av     = (const float*)d_in[24];
    const float* Wq_ao     = (const float*)d_in[25];
    const float* Wo_ao     = (const float*)d_in[26];
    const float* Wq_cand   = (const float*)d_in[27];
    float* out = (float*)d_out;

    cudaFuncSetAttribute(gemm_tc_kernel,
                         cudaFuncAttributeMaxDynamicSharedMemorySize, GEMM_SMEM);
    cudaFuncSetAttribute(attn_ctx_kernel,
                         cudaFuncAttributeMaxDynamicSharedMemorySize, CTX_SMEM);

    float* scr = nullptr;
    cudaGetSymbolAddress((void**)&scr, g_scratch);

    // 1) action embeds: tanh(action @ W_emb^T + b) -> Xv[:, :64] and Xo[:, :64]
    gemm_tc(action, W_emb, ANGLE, ANGLE, ANGLE, nullptr, nullptr, 0, 0, 0,
            scr + O_XV, INDIM, BATCH, EMB, scr + O_XO, INDIM, b_emb, 1);

    // 2) attention targets
    gemm_tc(prev_h1_o, Wq_dense, HID, HID, HID, nullptr, nullptr, 0, 0, 0,
            scr + O_TDENSE, FEAT, BATCH, FEAT);
    gemm_tc(prev_h1_v, Wq_feat, HID, HID, HID, nullptr, nullptr, 0, 0, 0,
            scr + O_TFEAT, FEAT, BATCH, FEAT);

    // 3) fused object/feature attention -> Xo[:,64:], Xv[:,64:]
    attn_obj_kernel<<<BATCH, 256>>>(denseObj, scr + O_TDENSE, obj_mask,
                                    scr + O_XO + EMB, INDIM);
    attn_obj_kernel<<<BATCH, 256>>>(feature, scr + O_TFEAT, nullptr,
                                    scr + O_XV + EMB, INDIM);

    // 4) LSTM gates: fused input + recurrent GEMM (two-segment K)
    gemm_tc(scr + O_XV, Wih_v, INDIM, INDIM, INDIM,
            prev_h1_v, Whh_v, HID, HID, HID,
            scr + O_GV, GATES, BATCH, GATES);
    gemm_tc(scr + O_XO, Wih_o, INDIM, INDIM, INDIM,
            prev_h1_o, Whh_o, HID, HID, HID,
            scr + O_GO, GATES, BATCH, GATES);

    // 5) LSTM cells (both use c_0_o per reference)
    lstm_cell_kernel<<<(BATCH * HID) / 256, 256>>>(
        scr + O_GV, bih_v, bhh_v, c_0_o, out + OFF_H1V, out + OFF_C1V,
        scr + O_HCV + HID, 2 * HID);
    lstm_cell_kernel<<<(BATCH * HID) / 256, 256>>>(
        scr + O_GO, bih_o, bhh_o, c_0_o, out + OFF_H1O, out + OFF_C1O,
        scr + O_HCO + HID, 2 * HID);

    // 6) ctx attention targets
    gemm_tc(out + OFF_H1V, Wq_av, HID, HID, HID, nullptr, nullptr, 0, 0, 0,
            scr + O_TAVV, HID, BATCH, HID);
    gemm_tc(out + OFF_H1O, Wq_ao, HID, HID, HID, nullptr, nullptr, 0, 0, 0,
            scr + O_TAVO, HID, BATCH, HID);

    // 7) fused masked ctx attention (v + o) -> wctx into concat buffers
    attn_ctx_kernel<<<BATCH, 256, CTX_SMEM>>>(
        ctx, scr + O_TAVV, scr + O_TAVO, ctx_mask,
        scr + O_HCV, scr + O_HCO, 2 * HID);

    // 8) h_tilde = tanh([wctx, h1] @ Wo^T) -> d_out + cand-concat buffer
    gemm_tc(scr + O_HCV, Wo_av, 2 * HID, 2 * HID, 2 * HID, nullptr, nullptr, 0, 0, 0,
            out + OFF_HTV, HID, BATCH, HID, scr + O_HC2, 2 * HID, nullptr, 1);
    gemm_tc(scr + O_HCO, Wo_ao, 2 * HID, 2 * HID, 2 * HID, nullptr, nullptr, 0, 0, 0,
            out + OFF_HTO, HID, BATCH, HID, scr + O_HC2 + HID, 2 * HID, nullptr, 1);

    // 9) candidate target + logits
    gemm_tc(scr + O_HC2, Wq_cand, 2 * HID, 2 * HID, 2 * HID, nullptr, nullptr, 0, 0, 0,
            scr + O_TCAND, FEAT, BATCH, FEAT);
    cand_logits_kernel<<<(BATCH * NC * 32) / 256, 256>>>(
        cand_feat, scr + O_TCAND, out + OFF_LOGIT);
}